// round 7
// baseline (speedup 1.0000x reference)
#include <cuda_runtime.h>
#include <cuda_fp16.h>
#include <math.h>
#include <stdint.h>

#define NTOK 2048
#define DIM  768
#define FF   3072
#define NE   8
#define NL   4
#define NA   (NTOK*2)

// smem per stage (halves): sAh[128*40], sAl, sBh[128*40], sBl
#define AWH 40
#define STAGE_H (4*128*40)           // 20480 halves = 40KB
#define SMEM_DYN (2*STAGE_H*2)       // 81920 B

// ---------------- scratch (static device globals; no allocation) -------------
__device__ float g_h   [NTOK*DIM];
__device__ float g_xln [NTOK*DIM];
__device__ float g_tmp [NTOK*DIM];
__device__ float g_H1  [(size_t)NA*FF];
__device__ float g_Y   [NA*DIM];
__device__ int   g_counts[NL*NE];
__device__ int   g_cursor[NL*NE];
__device__ int   g_off   [NL*(NE+1)];
__device__ int   g_tok [NA];
__device__ int   g_pair[NA];
__device__ float g_gw  [NA];
__device__ int   g_re  [NTOK*2];
__device__ float g_rw  [NTOK*2];

// ---------------- helpers ----------------------------------------------------
__device__ __forceinline__ void h2split(float a, float b, uint32_t& hi, uint32_t& lo) {
    __half ha = __float2half_rn(a), hb = __float2half_rn(b);
    float ra = a - __half2float(ha);
    float rb = b - __half2float(hb);
    __half la = __float2half_rn(ra), lb = __float2half_rn(rb);
    hi = (uint32_t)__half_as_ushort(ha) | ((uint32_t)__half_as_ushort(hb) << 16);
    lo = (uint32_t)__half_as_ushort(la) | ((uint32_t)__half_as_ushort(lb) << 16);
}

#define MMAH(acc, a, b0v, b1v) \
    asm volatile("mma.sync.aligned.m16n8k16.row.col.f32.f16.f16.f32 " \
        "{%0,%1,%2,%3},{%4,%5,%6,%7},{%8,%9},{%0,%1,%2,%3};" \
        : "+f"((acc)[0]), "+f"((acc)[1]), "+f"((acc)[2]), "+f"((acc)[3]) \
        : "r"((a)[0]), "r"((a)[1]), "r"((a)[2]), "r"((a)[3]), "r"(b0v), "r"(b1v))

__global__ void zero_k() {
    int i = threadIdx.x;
    if (i < NL*NE) { g_counts[i] = 0; g_cursor[i] = 0; }
}

// ---------------- LayerNorm: warp-per-token, no block syncs ------------------
__global__ void ln_gate(const float* __restrict__ in, float* __restrict__ out,
                        const float* __restrict__ gam, const float* __restrict__ bet,
                        const float* __restrict__ wg, int layer)
{
    const int wid = threadIdx.x >> 5, lane = threadIdx.x & 31;
    const int t = blockIdx.x*8 + wid;
    const float* row = in + (size_t)t*DIM;

    float v[24];
    float sum = 0.f, ssq = 0.f;
    #pragma unroll
    for (int i = 0; i < 6; i++) {
        float4 x4 = *(const float4*)(row + lane*4 + i*128);
        v[4*i] = x4.x; v[4*i+1] = x4.y; v[4*i+2] = x4.z; v[4*i+3] = x4.w;
        sum += x4.x + x4.y + x4.z + x4.w;
        ssq += x4.x*x4.x + x4.y*x4.y + x4.z*x4.z + x4.w*x4.w;
    }
    #pragma unroll
    for (int o = 16; o > 0; o >>= 1) {
        sum += __shfl_xor_sync(0xffffffffu, sum, o);
        ssq += __shfl_xor_sync(0xffffffffu, ssq, o);
    }
    const float mu = sum * (1.f/DIM);
    const float var = ssq * (1.f/DIM) - mu*mu;
    const float rstd = rsqrtf(var + 1e-5f);

    #pragma unroll
    for (int i = 0; i < 6; i++) {
        const int d = lane*4 + i*128;
        float4 gm = *(const float4*)(gam + d);
        float4 bt = *(const float4*)(bet + d);
        float4 o4;
        o4.x = (v[4*i]   - mu)*rstd*gm.x + bt.x;
        o4.y = (v[4*i+1] - mu)*rstd*gm.y + bt.y;
        o4.z = (v[4*i+2] - mu)*rstd*gm.z + bt.z;
        o4.w = (v[4*i+3] - mu)*rstd*gm.w + bt.w;
        v[4*i] = o4.x; v[4*i+1] = o4.y; v[4*i+2] = o4.z; v[4*i+3] = o4.w;
        *(float4*)(out + (size_t)t*DIM + d) = o4;
    }
    if (!wg) return;

    float acc[8] = {0,0,0,0,0,0,0,0};
    #pragma unroll
    for (int i = 0; i < 6; i++) {
        #pragma unroll
        for (int j = 0; j < 4; j++) {
            const int d = lane*4 + i*128 + j;
            const float o = v[4*i + j];
            float4 w0 = *(const float4*)(wg + d*8);
            float4 w1 = *(const float4*)(wg + d*8 + 4);
            acc[0] += o*w0.x; acc[1] += o*w0.y; acc[2] += o*w0.z; acc[3] += o*w0.w;
            acc[4] += o*w1.x; acc[5] += o*w1.y; acc[6] += o*w1.z; acc[7] += o*w1.w;
        }
    }
    #pragma unroll
    for (int o = 16; o > 0; o >>= 1)
        #pragma unroll
        for (int k = 0; k < 8; k++)
            acc[k] += __shfl_xor_sync(0xffffffffu, acc[k], o);

    if (lane == 0) {
        float v0 = -1e30f; int e0 = 0;
        #pragma unroll
        for (int e = 0; e < NE; e++) if (acc[e] > v0) { v0 = acc[e]; e0 = e; }
        float v1 = -1e30f; int e1 = 0;
        #pragma unroll
        for (int e = 0; e < NE; e++) if (e != e0 && acc[e] > v1) { v1 = acc[e]; e1 = e; }
        float ex  = expf(v1 - v0);
        float inv = 1.f / (1.f + ex);
        g_re[2*t] = e0;  g_re[2*t+1] = e1;
        g_rw[2*t] = inv; g_rw[2*t+1] = ex * inv;
        atomicAdd(&g_counts[layer*NE + e0], 1);
        atomicAdd(&g_counts[layer*NE + e1], 1);
    }
}

// fused scan + scatter (single block)
__global__ void scan_scatter(int layer) {
    __shared__ int soff[NE];
    if (threadIdx.x == 0) {
        int s = 0;
        for (int e = 0; e < NE; e++) {
            soff[e] = s;
            g_off[layer*(NE+1) + e] = s;
            s += g_counts[layer*NE + e];
        }
        g_off[layer*(NE+1) + NE] = s;
    }
    __syncthreads();
    for (int t = threadIdx.x; t < NTOK; t += blockDim.x) {
        #pragma unroll
        for (int k = 0; k < 2; k++) {
            int e = g_re[2*t + k];
            int p = atomicAdd(&g_cursor[layer*NE + e], 1);
            int i = soff[e] + p;
            g_tok[i]  = t;
            g_pair[i] = 2*t + k;
            g_gw[i]   = g_rw[2*t + k];
        }
    }
}

__global__ void combine_k() {
    int idx = blockIdx.x * 256 + threadIdx.x;
    int t = idx / DIM, d = idx - t*DIM;
    float v = g_h[idx];
    v = v + g_Y[(size_t)(2*t)*DIM + d];
    v = v + g_Y[(size_t)(2*t + 1)*DIM + d];
    g_h[idx] = v;
}

// ---------------- 3x-fp16-split GEMM, reg-prefetch + smem double buffer ------
// C = A[M,K] * B[K,N] + bias;  A row-major fp32, B row-major [K,N] fp32.
// mode 0: plain; mode 1: A via g_tok, relu -> g_H1; mode 2: A=g_H1, gw*(.) -> g_Y
__global__ void __launch_bounds__(256, 2)
hm_gemm(int mode, int layer,
        const float* __restrict__ A, const float* __restrict__ Bsrc,
        const float* __restrict__ bias, float* __restrict__ outF,
        int M, int Nn, int Kd)
{
    extern __shared__ __half smh[];

    const int tid = threadIdx.x;
    const int lane = tid & 31, wid = tid >> 5;
    const int warpM = wid >> 2, warpN = wid & 3;
    const int g = lane >> 2, tg = lane & 3;
    const int n0 = blockIdx.x*128, m0 = blockIdx.y*128;

    int Mloc = M, base = 0;
    if (mode == 1 || mode == 2) {
        int e = blockIdx.z;
        Mloc = g_counts[layer*NE + e];
        if (m0 >= Mloc) return;
        base = g_off[layer*(NE+1) + e];
        Bsrc += (size_t)(layer*NE + e) * FF * DIM;
        bias += (size_t)(layer*NE + e) * ((mode == 1) ? FF : DIM);
    } else {
        if (m0 >= M) return;
    }

    // A loader: thread -> row (tid>>1), k-half (tid&1): 16 floats
    const int rowA = tid >> 1, halfA = tid & 1;
    const float* pA = nullptr;
    {
        int lm = m0 + rowA;
        if (lm < Mloc) {
            int idx;
            if (mode == 1)      idx = g_tok[base + lm];
            else if (mode == 2) idx = base + lm;
            else                idx = lm;
            pA = A + (size_t)idx*Kd + halfA*16;
        }
    }
    // B loader: thread -> n (tid&127), k-seg (tid>>7): 16 strided floats
    const int nB = tid & 127, segB = tid >> 7;
    const float* pB = Bsrc + n0 + nB + (size_t)segB*16*Nn;

    float acc[4][4][4];
    #pragma unroll
    for (int a = 0; a < 4; a++)
        #pragma unroll
        for (int b = 0; b < 4; b++)
            #pragma unroll
            for (int c = 0; c < 4; c++) acc[a][b][c] = 0.f;

    float areg[16], breg[16];

    #define FETCH(kt) do {                                                    \
        _Pragma("unroll")                                                     \
        for (int q = 0; q < 4; q++) {                                         \
            float4 v = make_float4(0.f,0.f,0.f,0.f);                          \
            if (pA) v = *(const float4*)(pA + (kt) + q*4);                    \
            areg[4*q] = v.x; areg[4*q+1] = v.y;                               \
            areg[4*q+2] = v.z; areg[4*q+3] = v.w;                             \
        }                                                                     \
        _Pragma("unroll")                                                     \
        for (int kk = 0; kk < 16; kk++)                                       \
            breg[kk] = pB[(size_t)(kt + kk)*Nn];                              \
    } while (0)

    #define STST(stage) do {                                                  \
        __half* bAh = smh + (stage)*STAGE_H;                                  \
        __half* bAl = bAh + 5120;                                             \
        __half* bBh = bAh + 10240;                                            \
        __half* bBl = bAh + 15360;                                            \
        int sa = rowA*AWH + halfA*16;                                         \
        _Pragma("unroll")                                                     \
        for (int q = 0; q < 4; q++) {                                         \
            uint32_t h0,l0,h1,l1;                                             \
            h2split(areg[4*q], areg[4*q+1], h0, l0);                          \
            h2split(areg[4*q+2], areg[4*q+3], h1, l1);                        \
            *(uint32_t*)(bAh + sa + q*4)     = h0;                            \
            *(uint32_t*)(bAh + sa + q*4 + 2) = h1;                            \
            *(uint32_t*)(bAl + sa + q*4)     = l0;                            \
            *(uint32_t*)(bAl + sa + q*4 + 2) = l1;                            \
        }                                                                     \
        int sb = nB*AWH + segB*16;                                            \
        _Pragma("unroll")                                                     \
        for (int w = 0; w < 8; w++) {                                         \
            uint32_t h, l;                                                    \
            h2split(breg[2*w], breg[2*w+1], h, l);                            \
            *(uint32_t*)(bBh + sb + 2*w) = h;                                 \
            *(uint32_t*)(bBl + sb + 2*w) = l;                                 \
        }                                                                     \
    } while (0)

    const int nch = Kd >> 5;
    FETCH(0);
    STST(0);

    for (int ch = 0; ch < nch; ch++) {
        __syncthreads();
        if (ch + 1 < nch) FETCH((ch + 1)*32);

        const __half* sAh = smh + (ch & 1)*STAGE_H;
        const __half* sAl = sAh + 5120;
        const __half* sBh = sAh + 10240;
        const __half* sBl = sAh + 15360;

        #pragma unroll
        for (int ks = 0; ks < 2; ks++) {
            const int k0 = ks*16;
            uint32_t bh0[4], bh1[4], bl0[4], bl1[4];
            #pragma unroll
            for (int nt = 0; nt < 4; nt++) {
                int n = warpN*32 + nt*8 + g;
                bh0[nt] = *(const uint32_t*)(sBh + n*AWH + k0 + 2*tg);
                bh1[nt] = *(const uint32_t*)(sBh + n*AWH + k0 + 8 + 2*tg);
                bl0[nt] = *(const uint32_t*)(sBl + n*AWH + k0 + 2*tg);
                bl1[nt] = *(const uint32_t*)(sBl + n*AWH + k0 + 8 + 2*tg);
            }
            #pragma unroll
            for (int mt = 0; mt < 4; mt++) {
                int ra = warpM*64 + mt*16 + g;
                uint32_t ah[4], al[4];
                ah[0] = *(const uint32_t*)(sAh + ra*AWH     + k0 + 2*tg);
                ah[1] = *(const uint32_t*)(sAh + (ra+8)*AWH + k0 + 2*tg);
                ah[2] = *(const uint32_t*)(sAh + ra*AWH     + k0 + 8 + 2*tg);
                ah[3] = *(const uint32_t*)(sAh + (ra+8)*AWH + k0 + 8 + 2*tg);
                al[0] = *(const uint32_t*)(sAl + ra*AWH     + k0 + 2*tg);
                al[1] = *(const uint32_t*)(sAl + (ra+8)*AWH + k0 + 2*tg);
                al[2] = *(const uint32_t*)(sAl + ra*AWH     + k0 + 8 + 2*tg);
                al[3] = *(const uint32_t*)(sAl + (ra+8)*AWH + k0 + 8 + 2*tg);
                #pragma unroll
                for (int nt = 0; nt < 4; nt++) {
                    MMAH(acc[mt][nt], ah, bh0[nt], bh1[nt]);
                    MMAH(acc[mt][nt], ah, bl0[nt], bl1[nt]);
                    MMAH(acc[mt][nt], al, bh0[nt], bh1[nt]);
                }
            }
        }
        if (ch + 1 < nch) STST((ch + 1) & 1);
    }
    #undef FETCH
    #undef STST

    // ---------------- epilogue ----------------
    #pragma unroll
    for (int mt = 0; mt < 4; mt++) {
        #pragma unroll
        for (int half_m = 0; half_m < 2; half_m++) {
            const int mrow = m0 + warpM*64 + mt*16 + g + half_m*8;
            if (mrow >= Mloc) continue;
            float gww = 1.f;
            size_t rowoff;
            if (mode == 1) {
                rowoff = (size_t)(base + mrow) * FF;
            } else if (mode == 2) {
                int gi = base + mrow;
                gww = g_gw[gi];
                rowoff = (size_t)g_pair[gi] * DIM;
            } else {
                rowoff = (size_t)mrow * Nn;
            }
            #pragma unroll
            for (int nt = 0; nt < 4; nt++) {
                const int col = n0 + warpN*32 + nt*8 + tg*2;
                float2 bs = *(const float2*)(bias + col);
                float v0 = acc[mt][nt][2*half_m]     + bs.x;
                float v1 = acc[mt][nt][2*half_m + 1] + bs.y;
                if (mode == 1) {
                    v0 = fmaxf(v0, 0.f); v1 = fmaxf(v1, 0.f);
                    *(float2*)(g_H1 + rowoff + col) = make_float2(v0, v1);
                } else if (mode == 2) {
                    *(float2*)(g_Y + rowoff + col) = make_float2(gww*v0, gww*v1);
                } else {
                    *(float2*)(outF + rowoff + col) = make_float2(v0, v1);
                }
            }
        }
    }
}

// ---------------- host -------------------------------------------------------
extern "C" void kernel_launch(void* const* d_in, const int* in_sizes, int n_in,
                              void* d_out, int out_size)
{
    (void)in_sizes; (void)n_in; (void)out_size;
    const float* x      = (const float*)d_in[0];
    const float* w_in   = (const float*)d_in[1];
    const float* b_in   = (const float*)d_in[2];
    const float* gi     = (const float*)d_in[3];
    const float* bi     = (const float*)d_in[4];
    const float* g_lnp  = (const float*)d_in[5];
    const float* be_lnp = (const float*)d_in[6];
    const float* wgp    = (const float*)d_in[7];
    const float* w1p    = (const float*)d_in[8];
    const float* b1p    = (const float*)d_in[9];
    const float* w2p    = (const float*)d_in[10];
    const float* b2p    = (const float*)d_in[11];
    const float* w_out  = (const float*)d_in[12];
    const float* b_out  = (const float*)d_in[13];
    const float* g_o    = (const float*)d_in[14];
    const float* be_o   = (const float*)d_in[15];

    float *hP, *tmpP, *xlnP, *h1P;
    cudaGetSymbolAddress((void**)&hP,   g_h);
    cudaGetSymbolAddress((void**)&tmpP, g_tmp);
    cudaGetSymbolAddress((void**)&xlnP, g_xln);
    cudaGetSymbolAddress((void**)&h1P,  g_H1);

    cudaFuncSetAttribute(hm_gemm, cudaFuncAttributeMaxDynamicSharedMemorySize, SMEM_DYN);

    zero_k<<<1, 64>>>();

    // input projection + LN -> residual h
    hm_gemm<<<dim3(DIM/128, NTOK/128), 256, SMEM_DYN>>>(
        0, 0, x, w_in, b_in, tmpP, NTOK, DIM, DIM);
    ln_gate<<<NTOK/8, 256>>>(tmpP, hP, gi, bi, nullptr, 0);

    for (int l = 0; l < NL; l++) {
        ln_gate<<<NTOK/8, 256>>>(hP, xlnP, g_lnp + (size_t)l*DIM, be_lnp + (size_t)l*DIM,
                                 wgp + (size_t)l*DIM*NE, l);
        scan_scatter<<<1, 1024>>>(l);
        hm_gemm<<<dim3(FF/128, NTOK/128, NE), 256, SMEM_DYN>>>(
            1, l, xlnP, w1p, b1p, nullptr, 0, FF, DIM);
        hm_gemm<<<dim3(DIM/128, NTOK/128, NE), 256, SMEM_DYN>>>(
            2, l, h1P, w2p, b2p, nullptr, 0, DIM, FF);
        combine_k<<<NTOK*DIM/256, 256>>>();
    }

    // output projection + LN -> d_out
    hm_gemm<<<dim3(DIM/128, NTOK/128), 256, SMEM_DYN>>>(
        0, 0, hP, w_out, b_out, tmpP, NTOK, DIM, DIM);
    ln_gate<<<NTOK/8, 256>>>(tmpP, (float*)d_out, g_o, be_o, nullptr, 0);
}

// round 8
// speedup vs baseline: 1.0218x; 1.0218x over previous
#include <cuda_runtime.h>
#include <cuda_fp16.h>
#include <math.h>
#include <stdint.h>

#define NTOK 2048
#define DIM  768
#define FF   3072
#define NE   8
#define NL   4
#define NA   (NTOK*2)

// smem (halves): 4 tiles of 128 rows x 72 (64 data + 8 pad)
#define AWH 72
#define TILE_H (128*AWH)             // 9216 halves
#define SMEM_DYN (4*TILE_H*2)        // 73728 B

// ---------------- scratch (static device globals; no allocation) -------------
__device__ float g_h   [NTOK*DIM];
__device__ float g_xln [NTOK*DIM];
__device__ float g_tmp [NTOK*DIM];
__device__ float g_H1  [(size_t)NA*FF];
__device__ float g_Y   [NA*DIM];
__device__ int   g_counts[NL*NE];
__device__ int   g_cursor[NL*NE];
__device__ int   g_off   [NL*(NE+1)];
__device__ int   g_tok [NA];
__device__ int   g_pair[NA];
__device__ float g_gw  [NA];
__device__ int   g_re  [NTOK*2];
__device__ float g_rw  [NTOK*2];

// ---------------- helpers ----------------------------------------------------
__device__ __forceinline__ void h2split(float a, float b, uint32_t& hi, uint32_t& lo) {
    __half ha = __float2half_rn(a), hb = __float2half_rn(b);
    float ra = a - __half2float(ha);
    float rb = b - __half2float(hb);
    __half la = __float2half_rn(ra), lb = __float2half_rn(rb);
    hi = (uint32_t)__half_as_ushort(ha) | ((uint32_t)__half_as_ushort(hb) << 16);
    lo = (uint32_t)__half_as_ushort(la) | ((uint32_t)__half_as_ushort(lb) << 16);
}

#define MMAH(acc, a, b0v, b1v) \
    asm volatile("mma.sync.aligned.m16n8k16.row.col.f32.f16.f16.f32 " \
        "{%0,%1,%2,%3},{%4,%5,%6,%7},{%8,%9},{%0,%1,%2,%3};" \
        : "+f"((acc)[0]), "+f"((acc)[1]), "+f"((acc)[2]), "+f"((acc)[3]) \
        : "r"((a)[0]), "r"((a)[1]), "r"((a)[2]), "r"((a)[3]), "r"(b0v), "r"(b1v))

__global__ void zero_k() {
    int i = threadIdx.x;
    if (i < NL*NE) { g_counts[i] = 0; g_cursor[i] = 0; }
}

// ---------------- LayerNorm: warp-per-token, no block syncs ------------------
__global__ void ln_gate(const float* __restrict__ in, float* __restrict__ out,
                        const float* __restrict__ gam, const float* __restrict__ bet,
                        const float* __restrict__ wg, int layer)
{
    const int wid = threadIdx.x >> 5, lane = threadIdx.x & 31;
    const int t = blockIdx.x*8 + wid;
    const float* row = in + (size_t)t*DIM;

    float v[24];
    float sum = 0.f, ssq = 0.f;
    #pragma unroll
    for (int i = 0; i < 6; i++) {
        float4 x4 = *(const float4*)(row + lane*4 + i*128);
        v[4*i] = x4.x; v[4*i+1] = x4.y; v[4*i+2] = x4.z; v[4*i+3] = x4.w;
        sum += x4.x + x4.y + x4.z + x4.w;
        ssq += x4.x*x4.x + x4.y*x4.y + x4.z*x4.z + x4.w*x4.w;
    }
    #pragma unroll
    for (int o = 16; o > 0; o >>= 1) {
        sum += __shfl_xor_sync(0xffffffffu, sum, o);
        ssq += __shfl_xor_sync(0xffffffffu, ssq, o);
    }
    const float mu = sum * (1.f/DIM);
    const float var = ssq * (1.f/DIM) - mu*mu;
    const float rstd = rsqrtf(var + 1e-5f);

    #pragma unroll
    for (int i = 0; i < 6; i++) {
        const int d = lane*4 + i*128;
        float4 gm = *(const float4*)(gam + d);
        float4 bt = *(const float4*)(bet + d);
        float4 o4;
        o4.x = (v[4*i]   - mu)*rstd*gm.x + bt.x;
        o4.y = (v[4*i+1] - mu)*rstd*gm.y + bt.y;
        o4.z = (v[4*i+2] - mu)*rstd*gm.z + bt.z;
        o4.w = (v[4*i+3] - mu)*rstd*gm.w + bt.w;
        v[4*i] = o4.x; v[4*i+1] = o4.y; v[4*i+2] = o4.z; v[4*i+3] = o4.w;
        *(float4*)(out + (size_t)t*DIM + d) = o4;
    }
    if (!wg) return;

    float acc[8] = {0,0,0,0,0,0,0,0};
    #pragma unroll
    for (int i = 0; i < 6; i++) {
        #pragma unroll
        for (int j = 0; j < 4; j++) {
            const int d = lane*4 + i*128 + j;
            const float o = v[4*i + j];
            float4 w0 = *(const float4*)(wg + d*8);
            float4 w1 = *(const float4*)(wg + d*8 + 4);
            acc[0] += o*w0.x; acc[1] += o*w0.y; acc[2] += o*w0.z; acc[3] += o*w0.w;
            acc[4] += o*w1.x; acc[5] += o*w1.y; acc[6] += o*w1.z; acc[7] += o*w1.w;
        }
    }
    #pragma unroll
    for (int o = 16; o > 0; o >>= 1)
        #pragma unroll
        for (int k = 0; k < 8; k++)
            acc[k] += __shfl_xor_sync(0xffffffffu, acc[k], o);

    if (lane == 0) {
        float v0 = -1e30f; int e0 = 0;
        #pragma unroll
        for (int e = 0; e < NE; e++) if (acc[e] > v0) { v0 = acc[e]; e0 = e; }
        float v1 = -1e30f; int e1 = 0;
        #pragma unroll
        for (int e = 0; e < NE; e++) if (e != e0 && acc[e] > v1) { v1 = acc[e]; e1 = e; }
        float ex  = expf(v1 - v0);
        float inv = 1.f / (1.f + ex);
        g_re[2*t] = e0;  g_re[2*t+1] = e1;
        g_rw[2*t] = inv; g_rw[2*t+1] = ex * inv;
        atomicAdd(&g_counts[layer*NE + e0], 1);
        atomicAdd(&g_counts[layer*NE + e1], 1);
    }
}

// fused scan + scatter (single block)
__global__ void scan_scatter(int layer) {
    __shared__ int soff[NE];
    if (threadIdx.x == 0) {
        int s = 0;
        for (int e = 0; e < NE; e++) {
            soff[e] = s;
            g_off[layer*(NE+1) + e] = s;
            s += g_counts[layer*NE + e];
        }
        g_off[layer*(NE+1) + NE] = s;
    }
    __syncthreads();
    for (int t = threadIdx.x; t < NTOK; t += blockDim.x) {
        #pragma unroll
        for (int k = 0; k < 2; k++) {
            int e = g_re[2*t + k];
            int p = atomicAdd(&g_cursor[layer*NE + e], 1);
            int i = soff[e] + p;
            g_tok[i]  = t;
            g_pair[i] = 2*t + k;
            g_gw[i]   = g_rw[2*t + k];
        }
    }
}

__global__ void combine_k() {
    int idx = blockIdx.x * 256 + threadIdx.x;
    int t = idx / DIM, d = idx - t*DIM;
    float v = g_h[idx];
    v = v + g_Y[(size_t)(2*t)*DIM + d];
    v = v + g_Y[(size_t)(2*t + 1)*DIM + d];
    g_h[idx] = v;
}

// ---------------- 3x-fp16-split GEMM (m16n8k16, 128x128 tile, KC=64) --------
// C = A[M,K] * B[K,N] + bias;  A row-major fp32, B row-major [K,N] fp32.
// mode 0: plain; mode 1: A via g_tok, relu -> g_H1; mode 2: A=g_H1, gw*(.) -> g_Y
__global__ void __launch_bounds__(256, 2)
hm_gemm(int mode, int layer,
        const float* __restrict__ A, const float* __restrict__ Bsrc,
        const float* __restrict__ bias, float* __restrict__ outF,
        int M, int Nn, int Kd)
{
    extern __shared__ __half smh[];
    __half* sAh = smh;
    __half* sAl = smh + TILE_H;
    __half* sBh = smh + 2*TILE_H;    // layout [n][k], row stride AWH halves
    __half* sBl = smh + 3*TILE_H;

    const int tid = threadIdx.x;
    const int lane = tid & 31, wid = tid >> 5;
    const int warpM = wid >> 2, warpN = wid & 3;
    const int g = lane >> 2, tg = lane & 3;
    const int n0 = blockIdx.x*128, m0 = blockIdx.y*128;

    int Mloc = M, base = 0;
    if (mode == 1 || mode == 2) {
        int e = blockIdx.z;
        Mloc = g_counts[layer*NE + e];
        if (m0 >= Mloc) return;
        base = g_off[layer*(NE+1) + e];
        Bsrc += (size_t)(layer*NE + e) * FF * DIM;
        bias += (size_t)(layer*NE + e) * ((mode == 1) ? FF : DIM);
    } else {
        if (m0 >= M) return;
    }

    // A loader: thread -> row (tid>>1), k-half (tid&1): 32 floats (8 float4)
    const int rowA = tid >> 1, halfA = tid & 1;
    const float* pA = nullptr;
    {
        int lm = m0 + rowA;
        if (lm < Mloc) {
            int idx;
            if (mode == 1)      idx = g_tok[base + lm];
            else if (mode == 2) idx = base + lm;
            else                idx = lm;
            pA = A + (size_t)idx*Kd + halfA*32;
        }
    }
    // B loader: thread -> n (tid&127), k-seg (tid>>7): 32 strided floats
    const int nB = tid & 127, segB = tid >> 7;
    const float* pB = Bsrc + n0 + nB + (size_t)segB*32*Nn;

    float acc[4][4][4];
    #pragma unroll
    for (int a = 0; a < 4; a++)
        #pragma unroll
        for (int b = 0; b < 4; b++)
            #pragma unroll
            for (int c = 0; c < 4; c++) acc[a][b][c] = 0.f;

    const int nch = Kd >> 6;
    for (int ch = 0; ch < nch; ch++) {
        const int kt = ch*64;
        __syncthreads();   // previous-iteration readers done
        // ---- A tile [128 rows x 64 k] -> split halves ----
        {
            int sa = rowA*AWH + halfA*32;
            #pragma unroll
            for (int q = 0; q < 8; q++) {
                float4 v = make_float4(0.f,0.f,0.f,0.f);
                if (pA) v = *(const float4*)(pA + kt + q*4);
                uint32_t h0,l0,h1,l1;
                h2split(v.x, v.y, h0, l0);
                h2split(v.z, v.w, h1, l1);
                *(uint32_t*)(sAh + sa + q*4)     = h0;
                *(uint32_t*)(sAh + sa + q*4 + 2) = h1;
                *(uint32_t*)(sAl + sa + q*4)     = l0;
                *(uint32_t*)(sAl + sa + q*4 + 2) = l1;
            }
        }
        // ---- B tile [64 k x 128 n] -> transposed split halves sB[n][k] ----
        // two 16-float batches to keep register footprint at R6 level
        {
            int sb = nB*AWH + segB*32;
            #pragma unroll
            for (int half_b = 0; half_b < 2; half_b++) {
                float bv[16];
                #pragma unroll
                for (int kk = 0; kk < 16; kk++)
                    bv[kk] = pB[(size_t)(kt + half_b*16 + kk)*Nn];
                #pragma unroll
                for (int w = 0; w < 8; w++) {
                    uint32_t h, l;
                    h2split(bv[2*w], bv[2*w+1], h, l);
                    *(uint32_t*)(sBh + sb + half_b*16 + 2*w) = h;
                    *(uint32_t*)(sBl + sb + half_b*16 + 2*w) = l;
                }
            }
        }
        __syncthreads();

        // ---- 4 k16-steps ----
        #pragma unroll
        for (int ks = 0; ks < 4; ks++) {
            const int k0 = ks*16;
            uint32_t bh0[4], bh1[4], bl0[4], bl1[4];
            #pragma unroll
            for (int nt = 0; nt < 4; nt++) {
                int n = warpN*32 + nt*8 + g;
                bh0[nt] = *(const uint32_t*)(sBh + n*AWH + k0 + 2*tg);
                bh1[nt] = *(const uint32_t*)(sBh + n*AWH + k0 + 8 + 2*tg);
                bl0[nt] = *(const uint32_t*)(sBl + n*AWH + k0 + 2*tg);
                bl1[nt] = *(const uint32_t*)(sBl + n*AWH + k0 + 8 + 2*tg);
            }
            #pragma unroll
            for (int mt = 0; mt < 4; mt++) {
                int ra = warpM*64 + mt*16 + g;
                uint32_t ah[4], al[4];
                ah[0] = *(const uint32_t*)(sAh + ra*AWH     + k0 + 2*tg);
                ah[1] = *(const uint32_t*)(sAh + (ra+8)*AWH + k0 + 2*tg);
                ah[2] = *(const uint32_t*)(sAh + ra*AWH     + k0 + 8 + 2*tg);
                ah[3] = *(const uint32_t*)(sAh + (ra+8)*AWH + k0 + 8 + 2*tg);
                al[0] = *(const uint32_t*)(sAl + ra*AWH     + k0 + 2*tg);
                al[1] = *(const uint32_t*)(sAl + (ra+8)*AWH + k0 + 2*tg);
                al[2] = *(const uint32_t*)(sAl + ra*AWH     + k0 + 8 + 2*tg);
                al[3] = *(const uint32_t*)(sAl + (ra+8)*AWH + k0 + 8 + 2*tg);
                #pragma unroll
                for (int nt = 0; nt < 4; nt++) {
                    MMAH(acc[mt][nt], ah, bh0[nt], bh1[nt]);
                    MMAH(acc[mt][nt], ah, bl0[nt], bl1[nt]);
                    MMAH(acc[mt][nt], al, bh0[nt], bh1[nt]);
                }
            }
        }
    }

    // ---------------- epilogue ----------------
    #pragma unroll
    for (int mt = 0; mt < 4; mt++) {
        #pragma unroll
        for (int half_m = 0; half_m < 2; half_m++) {
            const int mrow = m0 + warpM*64 + mt*16 + g + half_m*8;
            if (mrow >= Mloc) continue;
            float gww = 1.f;
            size_t rowoff;
            if (mode == 1) {
                rowoff = (size_t)(base + mrow) * FF;
            } else if (mode == 2) {
                int gi = base + mrow;
                gww = g_gw[gi];
                rowoff = (size_t)g_pair[gi] * DIM;
            } else {
                rowoff = (size_t)mrow * Nn;
            }
            #pragma unroll
            for (int nt = 0; nt < 4; nt++) {
                const int col = n0 + warpN*32 + nt*8 + tg*2;
                float2 bs = *(const float2*)(bias + col);
                float v0 = acc[mt][nt][2*half_m]     + bs.x;
                float v1 = acc[mt][nt][2*half_m + 1] + bs.y;
                if (mode == 1) {
                    v0 = fmaxf(v0, 0.f); v1 = fmaxf(v1, 0.f);
                    *(float2*)(g_H1 + rowoff + col) = make_float2(v0, v1);
                } else if (mode == 2) {
                    *(float2*)(g_Y + rowoff + col) = make_float2(gww*v0, gww*v1);
                } else {
                    *(float2*)(outF + rowoff + col) = make_float2(v0, v1);
                }
            }
        }
    }
}

// ---------------- host -------------------------------------------------------
extern "C" void kernel_launch(void* const* d_in, const int* in_sizes, int n_in,
                              void* d_out, int out_size)
{
    (void)in_sizes; (void)n_in; (void)out_size;
    const float* x      = (const float*)d_in[0];
    const float* w_in   = (const float*)d_in[1];
    const float* b_in   = (const float*)d_in[2];
    const float* gi     = (const float*)d_in[3];
    const float* bi     = (const float*)d_in[4];
    const float* g_lnp  = (const float*)d_in[5];
    const float* be_lnp = (const float*)d_in[6];
    const float* wgp    = (const float*)d_in[7];
    const float* w1p    = (const float*)d_in[8];
    const float* b1p    = (const float*)d_in[9];
    const float* w2p    = (const float*)d_in[10];
    const float* b2p    = (const float*)d_in[11];
    const float* w_out  = (const float*)d_in[12];
    const float* b_out  = (const float*)d_in[13];
    const float* g_o    = (const float*)d_in[14];
    const float* be_o   = (const float*)d_in[15];

    float *hP, *tmpP, *xlnP, *h1P;
    cudaGetSymbolAddress((void**)&hP,   g_h);
    cudaGetSymbolAddress((void**)&tmpP, g_tmp);
    cudaGetSymbolAddress((void**)&xlnP, g_xln);
    cudaGetSymbolAddress((void**)&h1P,  g_H1);

    cudaFuncSetAttribute(hm_gemm, cudaFuncAttributeMaxDynamicSharedMemorySize, SMEM_DYN);

    zero_k<<<1, 64>>>();

    // input projection + LN -> residual h
    hm_gemm<<<dim3(DIM/128, NTOK/128), 256, SMEM_DYN>>>(
        0, 0, x, w_in, b_in, tmpP, NTOK, DIM, DIM);
    ln_gate<<<NTOK/8, 256>>>(tmpP, hP, gi, bi, nullptr, 0);

    for (int l = 0; l < NL; l++) {
        ln_gate<<<NTOK/8, 256>>>(hP, xlnP, g_lnp + (size_t)l*DIM, be_lnp + (size_t)l*DIM,
                                 wgp + (size_t)l*DIM*NE, l);
        scan_scatter<<<1, 1024>>>(l);
        hm_gemm<<<dim3(FF/128, NTOK/128, NE), 256, SMEM_DYN>>>(
            1, l, xlnP, w1p, b1p, nullptr, 0, FF, DIM);
        hm_gemm<<<dim3(DIM/128, NTOK/128, NE), 256, SMEM_DYN>>>(
            2, l, h1P, w2p, b2p, nullptr, 0, DIM, FF);
        combine_k<<<NTOK*DIM/256, 256>>>();
    }

    // output projection + LN -> d_out
    hm_gemm<<<dim3(DIM/128, NTOK/128), 256, SMEM_DYN>>>(
        0, 0, hP, w_out, b_out, tmpP, NTOK, DIM, DIM);
    ln_gate<<<NTOK/8, 256>>>(tmpP, (float*)d_out, g_o, be_o, nullptr, 0);
}

// round 9
// speedup vs baseline: 1.0353x; 1.0132x over previous
#include <cuda_runtime.h>
#include <cuda_fp16.h>
#include <math.h>
#include <stdint.h>

#define NTOK 2048
#define DIM  768
#define FF   3072
#define NE   8
#define NL   4
#define NA   (NTOK*2)

#define AWH 40   // halves per smem row (32 data + 8 pad)

// ---------------- scratch (static device globals; no allocation) -------------
__device__ float g_h   [NTOK*DIM];
__device__ float g_xln [NTOK*DIM];
__device__ float g_tmp [NTOK*DIM];
__device__ float g_H1  [(size_t)NA*FF];
__device__ float g_Y   [NA*DIM];
__device__ int   g_counts[NL*NE];
__device__ int   g_cursor[NL*NE];
__device__ int   g_off   [NL*(NE+1)];
__device__ int   g_tok [NA];
__device__ int   g_pair[NA];
__device__ float g_gw  [NA];
__device__ int   g_re  [NTOK*2];
__device__ float g_rw  [NTOK*2];

// ---------------- helpers ----------------------------------------------------
__device__ __forceinline__ void h2split(float a, float b, uint32_t& hi, uint32_t& lo) {
    __half ha = __float2half_rn(a), hb = __float2half_rn(b);
    float ra = a - __half2float(ha);
    float rb = b - __half2float(hb);
    __half la = __float2half_rn(ra), lb = __float2half_rn(rb);
    hi = (uint32_t)__half_as_ushort(ha) | ((uint32_t)__half_as_ushort(hb) << 16);
    lo = (uint32_t)__half_as_ushort(la) | ((uint32_t)__half_as_ushort(lb) << 16);
}

#define MMAH(acc, a, b0v, b1v) \
    asm volatile("mma.sync.aligned.m16n8k16.row.col.f32.f16.f16.f32 " \
        "{%0,%1,%2,%3},{%4,%5,%6,%7},{%8,%9},{%0,%1,%2,%3};" \
        : "+f"((acc)[0]), "+f"((acc)[1]), "+f"((acc)[2]), "+f"((acc)[3]) \
        : "r"((a)[0]), "r"((a)[1]), "r"((a)[2]), "r"((a)[3]), "r"(b0v), "r"(b1v))

__global__ void zero_k() {
    int i = threadIdx.x;
    if (i < NL*NE) { g_counts[i] = 0; g_cursor[i] = 0; }
}

// ---------------- LayerNorm (+ optional residual-combine, gate) --------------
// one warp per token. If Yin: h := h + Y[2t] + Y[2t+1] (written back to hrow),
// then LN(h) -> out, then optional gating.
__global__ void ln_gate(const float* __restrict__ in, float* __restrict__ out,
                        const float* __restrict__ gam, const float* __restrict__ bet,
                        const float* __restrict__ wg, int layer,
                        const float* __restrict__ Yin, float* __restrict__ hout)
{
    const int wid = threadIdx.x >> 5, lane = threadIdx.x & 31;
    const int t = blockIdx.x*8 + wid;
    const float* row = in + (size_t)t*DIM;

    float v[24];
    float sum = 0.f, ssq = 0.f;
    #pragma unroll
    for (int i = 0; i < 6; i++) {
        const int d = lane*4 + i*128;
        float4 x4 = *(const float4*)(row + d);
        if (Yin) {
            float4 y0 = *(const float4*)(Yin + (size_t)(2*t)*DIM + d);
            float4 y1 = *(const float4*)(Yin + (size_t)(2*t + 1)*DIM + d);
            x4.x += y0.x + y1.x; x4.y += y0.y + y1.y;
            x4.z += y0.z + y1.z; x4.w += y0.w + y1.w;
            *(float4*)(hout + (size_t)t*DIM + d) = x4;
        }
        v[4*i] = x4.x; v[4*i+1] = x4.y; v[4*i+2] = x4.z; v[4*i+3] = x4.w;
        sum += x4.x + x4.y + x4.z + x4.w;
        ssq += x4.x*x4.x + x4.y*x4.y + x4.z*x4.z + x4.w*x4.w;
    }
    #pragma unroll
    for (int o = 16; o > 0; o >>= 1) {
        sum += __shfl_xor_sync(0xffffffffu, sum, o);
        ssq += __shfl_xor_sync(0xffffffffu, ssq, o);
    }
    const float mu = sum * (1.f/DIM);
    const float var = ssq * (1.f/DIM) - mu*mu;
    const float rstd = rsqrtf(var + 1e-5f);

    #pragma unroll
    for (int i = 0; i < 6; i++) {
        const int d = lane*4 + i*128;
        float4 gm = *(const float4*)(gam + d);
        float4 bt = *(const float4*)(bet + d);
        float4 o4;
        o4.x = (v[4*i]   - mu)*rstd*gm.x + bt.x;
        o4.y = (v[4*i+1] - mu)*rstd*gm.y + bt.y;
        o4.z = (v[4*i+2] - mu)*rstd*gm.z + bt.z;
        o4.w = (v[4*i+3] - mu)*rstd*gm.w + bt.w;
        v[4*i] = o4.x; v[4*i+1] = o4.y; v[4*i+2] = o4.z; v[4*i+3] = o4.w;
        *(float4*)(out + (size_t)t*DIM + d) = o4;
    }
    if (!wg) return;

    float acc[8] = {0,0,0,0,0,0,0,0};
    #pragma unroll
    for (int i = 0; i < 6; i++) {
        #pragma unroll
        for (int j = 0; j < 4; j++) {
            const int d = lane*4 + i*128 + j;
            const float o = v[4*i + j];
            float4 w0 = *(const float4*)(wg + d*8);
            float4 w1 = *(const float4*)(wg + d*8 + 4);
            acc[0] += o*w0.x; acc[1] += o*w0.y; acc[2] += o*w0.z; acc[3] += o*w0.w;
            acc[4] += o*w1.x; acc[5] += o*w1.y; acc[6] += o*w1.z; acc[7] += o*w1.w;
        }
    }
    #pragma unroll
    for (int o = 16; o > 0; o >>= 1)
        #pragma unroll
        for (int k = 0; k < 8; k++)
            acc[k] += __shfl_xor_sync(0xffffffffu, acc[k], o);

    if (lane == 0) {
        float v0 = -1e30f; int e0 = 0;
        #pragma unroll
        for (int e = 0; e < NE; e++) if (acc[e] > v0) { v0 = acc[e]; e0 = e; }
        float v1 = -1e30f; int e1 = 0;
        #pragma unroll
        for (int e = 0; e < NE; e++) if (e != e0 && acc[e] > v1) { v1 = acc[e]; e1 = e; }
        float ex  = expf(v1 - v0);
        float inv = 1.f / (1.f + ex);
        g_re[2*t] = e0;  g_re[2*t+1] = e1;
        g_rw[2*t] = inv; g_rw[2*t+1] = ex * inv;
        atomicAdd(&g_counts[layer*NE + e0], 1);
        atomicAdd(&g_counts[layer*NE + e1], 1);
    }
}

// fused scan + scatter (single block)
__global__ void scan_scatter(int layer) {
    __shared__ int soff[NE];
    if (threadIdx.x == 0) {
        int s = 0;
        for (int e = 0; e < NE; e++) {
            soff[e] = s;
            g_off[layer*(NE+1) + e] = s;
            s += g_counts[layer*NE + e];
        }
        g_off[layer*(NE+1) + NE] = s;
    }
    __syncthreads();
    for (int t = threadIdx.x; t < NTOK; t += blockDim.x) {
        #pragma unroll
        for (int k = 0; k < 2; k++) {
            int e = g_re[2*t + k];
            int p = atomicAdd(&g_cursor[layer*NE + e], 1);
            int i = soff[e] + p;
            g_tok[i]  = t;
            g_pair[i] = 2*t + k;
            g_gw[i]   = g_rw[2*t + k];
        }
    }
}

__global__ void combine_k() {
    int idx = blockIdx.x * 256 + threadIdx.x;
    int t = idx / DIM, d = idx - t*DIM;
    float v = g_h[idx];
    v = v + g_Y[(size_t)(2*t)*DIM + d];
    v = v + g_Y[(size_t)(2*t + 1)*DIM + d];
    g_h[idx] = v;
}

// ---------------- 3x-fp16-split GEMM (m16n8k16, BMx128 tile, KC=32) ----------
// R6-proven mainloop; BM templated for wave balance (128 or 64).
// mode 0: plain; mode 1: A via g_tok, relu -> g_H1; mode 2: A=g_H1, gw*(.) -> g_Y
template<int BM>
__global__ void __launch_bounds__(256, 2)
hm_gemm(int mode, int layer,
        const float* __restrict__ A, const float* __restrict__ Bsrc,
        const float* __restrict__ bias, float* __restrict__ outF,
        int M, int Nn, int Kd)
{
    constexpr int MT  = BM/32;        // m16 tiles per warpM
    constexpr int TPR = 256/BM;       // threads per A row
    constexpr int CH  = 32/TPR;       // floats per A-loader thread
    constexpr int ATILE = BM*AWH;     // halves

    extern __shared__ __half smh[];
    __half* sAh = smh;
    __half* sAl = smh + ATILE;
    __half* sBh = smh + 2*ATILE;            // [n][k], stride AWH
    __half* sBl = smh + 2*ATILE + 128*AWH;

    const int tid = threadIdx.x;
    const int lane = tid & 31, wid = tid >> 5;
    const int warpM = wid >> 2, warpN = wid & 3;
    const int g = lane >> 2, tg = lane & 3;
    const int n0 = blockIdx.x*128, m0 = blockIdx.y*BM;

    int Mloc = M, base = 0;
    if (mode == 1 || mode == 2) {
        int e = blockIdx.z;
        Mloc = g_counts[layer*NE + e];
        if (m0 >= Mloc) return;
        base = g_off[layer*(NE+1) + e];
        Bsrc += (size_t)(layer*NE + e) * FF * DIM;
        bias += (size_t)(layer*NE + e) * ((mode == 1) ? FF : DIM);
    } else {
        if (m0 >= M) return;
    }

    // A loader: thread -> row (tid/TPR), sub-chunk (tid%TPR) of CH floats
    const int rowA = tid / TPR, subA = tid % TPR;
    const float* pA = nullptr;
    {
        int lm = m0 + rowA;
        if (lm < Mloc) {
            int idx;
            if (mode == 1)      idx = g_tok[base + lm];
            else if (mode == 2) idx = base + lm;
            else                idx = lm;
            pA = A + (size_t)idx*Kd + subA*CH;
        }
    }
    // B loader: thread -> n (tid&127), k-seg (tid>>7) of 16
    const int nB = tid & 127, segB = tid >> 7;
    const float* pB = Bsrc + n0 + nB + (size_t)segB*16*Nn;

    float acc[MT][4][4];
    #pragma unroll
    for (int a = 0; a < MT; a++)
        #pragma unroll
        for (int b = 0; b < 4; b++)
            #pragma unroll
            for (int c = 0; c < 4; c++) acc[a][b][c] = 0.f;

    for (int kt = 0; kt < Kd; kt += 32) {
        __syncthreads();
        // ---- A tile [BM x 32] -> split halves ----
        {
            int sa = rowA*AWH + subA*CH;
            #pragma unroll
            for (int q = 0; q < CH/4; q++) {
                float4 v = make_float4(0.f,0.f,0.f,0.f);
                if (pA) v = *(const float4*)(pA + kt + q*4);
                uint32_t h0,l0,h1,l1;
                h2split(v.x, v.y, h0, l0);
                h2split(v.z, v.w, h1, l1);
                *(uint32_t*)(sAh + sa + q*4)     = h0;
                *(uint32_t*)(sAh + sa + q*4 + 2) = h1;
                *(uint32_t*)(sAl + sa + q*4)     = l0;
                *(uint32_t*)(sAl + sa + q*4 + 2) = l1;
            }
        }
        // ---- B tile [32 k x 128 n] -> transposed split halves sB[n][k] ----
        {
            float bv[16];
            #pragma unroll
            for (int kk = 0; kk < 16; kk++)
                bv[kk] = pB[(size_t)(kt + kk)*Nn];
            int sb = nB*AWH + segB*16;
            #pragma unroll
            for (int w = 0; w < 8; w++) {
                uint32_t h, l;
                h2split(bv[2*w], bv[2*w+1], h, l);
                *(uint32_t*)(sBh + sb + 2*w) = h;
                *(uint32_t*)(sBl + sb + 2*w) = l;
            }
        }
        __syncthreads();

        // ---- 2 k16-steps ----
        #pragma unroll
        for (int ks = 0; ks < 2; ks++) {
            const int k0 = ks*16;
            uint32_t bh0[4], bh1[4], bl0[4], bl1[4];
            #pragma unroll
            for (int nt = 0; nt < 4; nt++) {
                int n = warpN*32 + nt*8 + g;
                bh0[nt] = *(const uint32_t*)(sBh + n*AWH + k0 + 2*tg);
                bh1[nt] = *(const uint32_t*)(sBh + n*AWH + k0 + 8 + 2*tg);
                bl0[nt] = *(const uint32_t*)(sBl + n*AWH + k0 + 2*tg);
                bl1[nt] = *(const uint32_t*)(sBl + n*AWH + k0 + 8 + 2*tg);
            }
            #pragma unroll
            for (int mt = 0; mt < MT; mt++) {
                int ra = warpM*(BM/2) + mt*16 + g;
                uint32_t ah[4], al[4];
                ah[0] = *(const uint32_t*)(sAh + ra*AWH     + k0 + 2*tg);
                ah[1] = *(const uint32_t*)(sAh + (ra+8)*AWH + k0 + 2*tg);
                ah[2] = *(const uint32_t*)(sAh + ra*AWH     + k0 + 8 + 2*tg);
                ah[3] = *(const uint32_t*)(sAh + (ra+8)*AWH + k0 + 8 + 2*tg);
                al[0] = *(const uint32_t*)(sAl + ra*AWH     + k0 + 2*tg);
                al[1] = *(const uint32_t*)(sAl + (ra+8)*AWH + k0 + 2*tg);
                al[2] = *(const uint32_t*)(sAl + ra*AWH     + k0 + 8 + 2*tg);
                al[3] = *(const uint32_t*)(sAl + (ra+8)*AWH + k0 + 8 + 2*tg);
                #pragma unroll
                for (int nt = 0; nt < 4; nt++) {
                    MMAH(acc[mt][nt], ah, bh0[nt], bh1[nt]);
                    MMAH(acc[mt][nt], ah, bl0[nt], bl1[nt]);
                    MMAH(acc[mt][nt], al, bh0[nt], bh1[nt]);
                }
            }
        }
    }

    // ---------------- epilogue ----------------
    #pragma unroll
    for (int mt = 0; mt < MT; mt++) {
        #pragma unroll
        for (int half_m = 0; half_m < 2; half_m++) {
            const int mrow = m0 + warpM*(BM/2) + mt*16 + g + half_m*8;
            if (mrow >= Mloc) continue;
            float gww = 1.f;
            size_t rowoff;
            if (mode == 1) {
                rowoff = (size_t)(base + mrow) * FF;
            } else if (mode == 2) {
                int gi = base + mrow;
                gww = g_gw[gi];
                rowoff = (size_t)g_pair[gi] * DIM;
            } else {
                rowoff = (size_t)mrow * Nn;
            }
            #pragma unroll
            for (int nt = 0; nt < 4; nt++) {
                const int col = n0 + warpN*32 + nt*8 + tg*2;
                float2 bs = *(const float2*)(bias + col);
                float v0 = acc[mt][nt][2*half_m]     + bs.x;
                float v1 = acc[mt][nt][2*half_m + 1] + bs.y;
                if (mode == 1) {
                    v0 = fmaxf(v0, 0.f); v1 = fmaxf(v1, 0.f);
                    *(float2*)(g_H1 + rowoff + col) = make_float2(v0, v1);
                } else if (mode == 2) {
                    *(float2*)(g_Y + rowoff + col) = make_float2(gww*v0, gww*v1);
                } else {
                    *(float2*)(outF + rowoff + col) = make_float2(v0, v1);
                }
            }
        }
    }
}

#define SMEM128 ((4*128*AWH)*2)          // 40960 B
#define SMEM64  ((2*64*AWH + 2*128*AWH)*2) // 30720 B

// ---------------- host -------------------------------------------------------
extern "C" void kernel_launch(void* const* d_in, const int* in_sizes, int n_in,
                              void* d_out, int out_size)
{
    (void)in_sizes; (void)n_in; (void)out_size;
    const float* x      = (const float*)d_in[0];
    const float* w_in   = (const float*)d_in[1];
    const float* b_in   = (const float*)d_in[2];
    const float* gi     = (const float*)d_in[3];
    const float* bi     = (const float*)d_in[4];
    const float* g_lnp  = (const float*)d_in[5];
    const float* be_lnp = (const float*)d_in[6];
    const float* wgp    = (const float*)d_in[7];
    const float* w1p    = (const float*)d_in[8];
    const float* b1p    = (const float*)d_in[9];
    const float* w2p    = (const float*)d_in[10];
    const float* b2p    = (const float*)d_in[11];
    const float* w_out  = (const float*)d_in[12];
    const float* b_out  = (const float*)d_in[13];
    const float* g_o    = (const float*)d_in[14];
    const float* be_o   = (const float*)d_in[15];

    float *hP, *tmpP, *xlnP, *h1P, *YP;
    cudaGetSymbolAddress((void**)&hP,   g_h);
    cudaGetSymbolAddress((void**)&tmpP, g_tmp);
    cudaGetSymbolAddress((void**)&xlnP, g_xln);
    cudaGetSymbolAddress((void**)&h1P,  g_H1);
    cudaGetSymbolAddress((void**)&YP,   g_Y);

    cudaFuncSetAttribute(hm_gemm<128>, cudaFuncAttributeMaxDynamicSharedMemorySize, SMEM128);
    cudaFuncSetAttribute(hm_gemm<64>,  cudaFuncAttributeMaxDynamicSharedMemorySize, SMEM64);

    zero_k<<<1, 64>>>();

    // input projection + LN -> residual h
    hm_gemm<64><<<dim3(DIM/128, NTOK/64), 256, SMEM64>>>(
        0, 0, x, w_in, b_in, tmpP, NTOK, DIM, DIM);
    ln_gate<<<NTOK/8, 256>>>(tmpP, hP, gi, bi, nullptr, 0, nullptr, nullptr);

    for (int l = 0; l < NL; l++) {
        // LN (+ combine of previous layer's Y for l>0) + gate
        ln_gate<<<NTOK/8, 256>>>(hP, xlnP, g_lnp + (size_t)l*DIM, be_lnp + (size_t)l*DIM,
                                 wgp + (size_t)l*DIM*NE, l,
                                 (l > 0) ? YP : nullptr, hP);
        scan_scatter<<<1, 1024>>>(l);
        hm_gemm<128><<<dim3(FF/128, NTOK/128, NE), 256, SMEM128>>>(
            1, l, xlnP, w1p, b1p, nullptr, 0, FF, DIM);
        hm_gemm<64><<<dim3(DIM/128, NTOK/64, NE), 256, SMEM64>>>(
            2, l, h1P, w2p, b2p, nullptr, 0, DIM, FF);
    }
    combine_k<<<NTOK*DIM/256, 256>>>();   // final layer residual

    // output projection + LN -> d_out
    hm_gemm<64><<<dim3(DIM/128, NTOK/64), 256, SMEM64>>>(
        0, 0, hP, w_out, b_out, tmpP, NTOK, DIM, DIM);
    ln_gate<<<NTOK/8, 256>>>(tmpP, (float*)d_out, g_o, be_o, nullptr, 0, nullptr, nullptr);
}

// round 10
// speedup vs baseline: 1.1443x; 1.1053x over previous
#include <cuda_runtime.h>
#include <cuda_fp16.h>
#include <math.h>
#include <stdint.h>

#define NTOK 2048
#define DIM  768
#define FF   3072
#define NE   8
#define NL   4
#define NA   (NTOK*2)

// smem (halves): sAh[128*40], sAl, sBh[128*40], sBl   (row stride 40 halves)
#define AWH 40
#define SMEM_DYN (4*128*40*2)

// ---------------- scratch (static device globals; no allocation) -------------
__device__ float g_h   [NTOK*DIM];
__device__ float g_xln [NTOK*DIM];
__device__ float g_tmp [NTOK*DIM];
__device__ float g_H1  [(size_t)NA*FF];
__device__ float g_Y   [NA*DIM];
__device__ int   g_counts[NL*NE];
__device__ int   g_cursor[NL*NE];
__device__ int   g_off   [NL*(NE+1)];
__device__ int   g_tok [NA];
__device__ int   g_pair[NA];
__device__ float g_gw  [NA];
__device__ int   g_re  [NTOK*2];
__device__ float g_rw  [NTOK*2];

// ---------------- helpers ----------------------------------------------------
__device__ __forceinline__ void h2split(float a, float b, uint32_t& hi, uint32_t& lo) {
    __half ha = __float2half_rn(a), hb = __float2half_rn(b);
    float ra = a - __half2float(ha);
    float rb = b - __half2float(hb);
    __half la = __float2half_rn(ra), lb = __float2half_rn(rb);
    hi = (uint32_t)__half_as_ushort(ha) | ((uint32_t)__half_as_ushort(hb) << 16);
    lo = (uint32_t)__half_as_ushort(la) | ((uint32_t)__half_as_ushort(lb) << 16);
}

#define MMAH(acc, a, b0v, b1v) \
    asm volatile("mma.sync.aligned.m16n8k16.row.col.f32.f16.f16.f32 " \
        "{%0,%1,%2,%3},{%4,%5,%6,%7},{%8,%9},{%0,%1,%2,%3};" \
        : "+f"((acc)[0]), "+f"((acc)[1]), "+f"((acc)[2]), "+f"((acc)[3]) \
        : "r"((a)[0]), "r"((a)[1]), "r"((a)[2]), "r"((a)[3]), "r"(b0v), "r"(b1v))

__global__ void zero_k() {
    int i = threadIdx.x;
    if (i < NL*NE) { g_counts[i] = 0; g_cursor[i] = 0; }
}

// ---------------- LayerNorm (+ optional residual-combine, gate) --------------
// one warp per token. If Yin: h := h + Y[2t] + Y[2t+1] (written to hout),
// then LN -> out, then optional gating/routing.
__global__ void ln_gate(const float* __restrict__ in, float* __restrict__ out,
                        const float* __restrict__ gam, const float* __restrict__ bet,
                        const float* __restrict__ wg, int layer,
                        const float* __restrict__ Yin, float* __restrict__ hout)
{
    const int wid = threadIdx.x >> 5, lane = threadIdx.x & 31;
    const int t = blockIdx.x*8 + wid;
    const float* row = in + (size_t)t*DIM;

    float v[24];
    float sum = 0.f, ssq = 0.f;
    #pragma unroll
    for (int i = 0; i < 6; i++) {
        const int d = lane*4 + i*128;
        float4 x4 = *(const float4*)(row + d);
        if (Yin) {
            float4 y0 = *(const float4*)(Yin + (size_t)(2*t)*DIM + d);
            float4 y1 = *(const float4*)(Yin + (size_t)(2*t + 1)*DIM + d);
            x4.x += y0.x + y1.x; x4.y += y0.y + y1.y;
            x4.z += y0.z + y1.z; x4.w += y0.w + y1.w;
            *(float4*)(hout + (size_t)t*DIM + d) = x4;
        }
        v[4*i] = x4.x; v[4*i+1] = x4.y; v[4*i+2] = x4.z; v[4*i+3] = x4.w;
        sum += x4.x + x4.y + x4.z + x4.w;
        ssq += x4.x*x4.x + x4.y*x4.y + x4.z*x4.z + x4.w*x4.w;
    }
    #pragma unroll
    for (int o = 16; o > 0; o >>= 1) {
        sum += __shfl_xor_sync(0xffffffffu, sum, o);
        ssq += __shfl_xor_sync(0xffffffffu, ssq, o);
    }
    const float mu = sum * (1.f/DIM);
    const float var = ssq * (1.f/DIM) - mu*mu;
    const float rstd = rsqrtf(var + 1e-5f);

    #pragma unroll
    for (int i = 0; i < 6; i++) {
        const int d = lane*4 + i*128;
        float4 gm = *(const float4*)(gam + d);
        float4 bt = *(const float4*)(bet + d);
        float4 o4;
        o4.x = (v[4*i]   - mu)*rstd*gm.x + bt.x;
        o4.y = (v[4*i+1] - mu)*rstd*gm.y + bt.y;
        o4.z = (v[4*i+2] - mu)*rstd*gm.z + bt.z;
        o4.w = (v[4*i+3] - mu)*rstd*gm.w + bt.w;
        v[4*i] = o4.x; v[4*i+1] = o4.y; v[4*i+2] = o4.z; v[4*i+3] = o4.w;
        *(float4*)(out + (size_t)t*DIM + d) = o4;
    }
    if (!wg) return;

    float acc[8] = {0,0,0,0,0,0,0,0};
    #pragma unroll
    for (int i = 0; i < 6; i++) {
        #pragma unroll
        for (int j = 0; j < 4; j++) {
            const int d = lane*4 + i*128 + j;
            const float o = v[4*i + j];
            float4 w0 = *(const float4*)(wg + d*8);
            float4 w1 = *(const float4*)(wg + d*8 + 4);
            acc[0] += o*w0.x; acc[1] += o*w0.y; acc[2] += o*w0.z; acc[3] += o*w0.w;
            acc[4] += o*w1.x; acc[5] += o*w1.y; acc[6] += o*w1.z; acc[7] += o*w1.w;
        }
    }
    #pragma unroll
    for (int o = 16; o > 0; o >>= 1)
        #pragma unroll
        for (int k = 0; k < 8; k++)
            acc[k] += __shfl_xor_sync(0xffffffffu, acc[k], o);

    if (lane == 0) {
        float v0 = -1e30f; int e0 = 0;
        #pragma unroll
        for (int e = 0; e < NE; e++) if (acc[e] > v0) { v0 = acc[e]; e0 = e; }
        float v1 = -1e30f; int e1 = 0;
        #pragma unroll
        for (int e = 0; e < NE; e++) if (e != e0 && acc[e] > v1) { v1 = acc[e]; e1 = e; }
        float ex  = expf(v1 - v0);
        float inv = 1.f / (1.f + ex);
        g_re[2*t] = e0;  g_re[2*t+1] = e1;
        g_rw[2*t] = inv; g_rw[2*t+1] = ex * inv;
        atomicAdd(&g_counts[layer*NE + e0], 1);
        atomicAdd(&g_counts[layer*NE + e1], 1);
    }
}

// fused scan + scatter (single block)
__global__ void scan_scatter(int layer) {
    __shared__ int soff[NE];
    if (threadIdx.x == 0) {
        int s = 0;
        for (int e = 0; e < NE; e++) {
            soff[e] = s;
            g_off[layer*(NE+1) + e] = s;
            s += g_counts[layer*NE + e];
        }
        g_off[layer*(NE+1) + NE] = s;
    }
    __syncthreads();
    for (int t = threadIdx.x; t < NTOK; t += blockDim.x) {
        #pragma unroll
        for (int k = 0; k < 2; k++) {
            int e = g_re[2*t + k];
            int p = atomicAdd(&g_cursor[layer*NE + e], 1);
            int i = soff[e] + p;
            g_tok[i]  = t;
            g_pair[i] = 2*t + k;
            g_gw[i]   = g_rw[2*t + k];
        }
    }
}

__global__ void combine_k() {
    int idx = blockIdx.x * 256 + threadIdx.x;
    int t = idx / DIM, d = idx - t*DIM;
    float v = g_h[idx];
    v = v + g_Y[(size_t)(2*t)*DIM + d];
    v = v + g_Y[(size_t)(2*t + 1)*DIM + d];
    g_h[idx] = v;
}

// ---------------- 3x-fp16-split GEMM (m16n8k16, 128x128 tile, KC=32) --------
// R6-proven mainloop, verbatim.
// mode 0: plain; mode 1: A via g_tok, relu -> g_H1; mode 2: A=g_H1, gw*(.) -> g_Y
__global__ void __launch_bounds__(256, 2)
hm_gemm(int mode, int layer,
        const float* __restrict__ A, const float* __restrict__ Bsrc,
        const float* __restrict__ bias, float* __restrict__ outF,
        int M, int Nn, int Kd)
{
    extern __shared__ __half smh[];
    __half* sAh = smh;
    __half* sAl = smh + 5120;
    __half* sBh = smh + 10240;   // layout [n][k]: n row stride AWH halves
    __half* sBl = smh + 15360;

    const int tid = threadIdx.x;
    const int lane = tid & 31, wid = tid >> 5;
    const int warpM = wid >> 2, warpN = wid & 3;
    const int g = lane >> 2, tg = lane & 3;
    const int n0 = blockIdx.x*128, m0 = blockIdx.y*128;

    int Mloc = M, base = 0;
    if (mode == 1 || mode == 2) {
        int e = blockIdx.z;
        Mloc = g_counts[layer*NE + e];
        if (m0 >= Mloc) return;
        base = g_off[layer*(NE+1) + e];
        Bsrc += (size_t)(layer*NE + e) * FF * DIM;
        bias += (size_t)(layer*NE + e) * ((mode == 1) ? FF : DIM);
    } else {
        if (m0 >= M) return;
    }

    // A loader: thread -> row (tid>>1), k-half (tid&1) (16 floats = 4 float4)
    const int rowA = tid >> 1, halfA = tid & 1;
    const float* pA = nullptr;
    {
        int lm = m0 + rowA;
        if (lm < Mloc) {
            int idx;
            if (mode == 1)      idx = g_tok[base + lm];
            else if (mode == 2) idx = base + lm;
            else                idx = lm;
            pA = A + (size_t)idx*Kd + halfA*16;
        }
    }
    // B loader: thread -> n (tid&127), k-seg (tid>>7) of 16
    const int nB = tid & 127, segB = tid >> 7;
    const float* pB = Bsrc + n0 + nB + (size_t)segB*16*Nn;

    float acc[4][4][4];
    #pragma unroll
    for (int a = 0; a < 4; a++)
        #pragma unroll
        for (int b = 0; b < 4; b++)
            #pragma unroll
            for (int c = 0; c < 4; c++) acc[a][b][c] = 0.f;

    for (int kt = 0; kt < Kd; kt += 32) {
        __syncthreads();   // previous-iteration readers done
        // ---- A tile [128 rows x 32 k] -> split halves ----
        {
            int sa = rowA*AWH + halfA*16;
            #pragma unroll
            for (int q = 0; q < 4; q++) {
                float4 v = make_float4(0.f,0.f,0.f,0.f);
                if (pA) v = *(const float4*)(pA + kt + q*4);
                uint32_t h0,l0,h1,l1;
                h2split(v.x, v.y, h0, l0);
                h2split(v.z, v.w, h1, l1);
                *(uint32_t*)(sAh + sa + q*4)     = h0;
                *(uint32_t*)(sAh + sa + q*4 + 2) = h1;
                *(uint32_t*)(sAl + sa + q*4)     = l0;
                *(uint32_t*)(sAl + sa + q*4 + 2) = l1;
            }
        }
        // ---- B tile [32 k x 128 n] -> transposed split halves sB[n][k] ----
        {
            float bv[16];
            #pragma unroll
            for (int kk = 0; kk < 16; kk++)
                bv[kk] = pB[(size_t)(kt + kk)*Nn];
            int sb = nB*AWH + segB*16;
            #pragma unroll
            for (int w = 0; w < 8; w++) {
                uint32_t h, l;
                h2split(bv[2*w], bv[2*w+1], h, l);
                *(uint32_t*)(sBh + sb + 2*w) = h;
                *(uint32_t*)(sBl + sb + 2*w) = l;
            }
        }
        __syncthreads();

        // ---- 2 k16-steps ----
        #pragma unroll
        for (int ks = 0; ks < 2; ks++) {
            const int k0 = ks*16;
            uint32_t bh0[4], bh1[4], bl0[4], bl1[4];
            #pragma unroll
            for (int nt = 0; nt < 4; nt++) {
                int n = warpN*32 + nt*8 + g;
                bh0[nt] = *(const uint32_t*)(sBh + n*AWH + k0 + 2*tg);
                bh1[nt] = *(const uint32_t*)(sBh + n*AWH + k0 + 8 + 2*tg);
                bl0[nt] = *(const uint32_t*)(sBl + n*AWH + k0 + 2*tg);
                bl1[nt] = *(const uint32_t*)(sBl + n*AWH + k0 + 8 + 2*tg);
            }
            #pragma unroll
            for (int mt = 0; mt < 4; mt++) {
                int ra = warpM*64 + mt*16 + g;
                uint32_t ah[4], al[4];
                ah[0] = *(const uint32_t*)(sAh + ra*AWH     + k0 + 2*tg);
                ah[1] = *(const uint32_t*)(sAh + (ra+8)*AWH + k0 + 2*tg);
                ah[2] = *(const uint32_t*)(sAh + ra*AWH     + k0 + 8 + 2*tg);
                ah[3] = *(const uint32_t*)(sAh + (ra+8)*AWH + k0 + 8 + 2*tg);
                al[0] = *(const uint32_t*)(sAl + ra*AWH     + k0 + 2*tg);
                al[1] = *(const uint32_t*)(sAl + (ra+8)*AWH + k0 + 2*tg);
                al[2] = *(const uint32_t*)(sAl + ra*AWH     + k0 + 8 + 2*tg);
                al[3] = *(const uint32_t*)(sAl + (ra+8)*AWH + k0 + 8 + 2*tg);
                #pragma unroll
                for (int nt = 0; nt < 4; nt++) {
                    MMAH(acc[mt][nt], ah, bh0[nt], bh1[nt]);
                    MMAH(acc[mt][nt], ah, bl0[nt], bl1[nt]);
                    MMAH(acc[mt][nt], al, bh0[nt], bh1[nt]);
                }
            }
        }
    }

    // ---------------- epilogue ----------------
    #pragma unroll
    for (int mt = 0; mt < 4; mt++) {
        #pragma unroll
        for (int half_m = 0; half_m < 2; half_m++) {
            const int mrow = m0 + warpM*64 + mt*16 + g + half_m*8;
            if (mrow >= Mloc) continue;
            float gww = 1.f;
            size_t rowoff;
            if (mode == 1) {
                rowoff = (size_t)(base + mrow) * FF;
            } else if (mode == 2) {
                int gi = base + mrow;
                gww = g_gw[gi];
                rowoff = (size_t)g_pair[gi] * DIM;
            } else {
                rowoff = (size_t)mrow * Nn;
            }
            #pragma unroll
            for (int nt = 0; nt < 4; nt++) {
                const int col = n0 + warpN*32 + nt*8 + tg*2;
                float2 bs = *(const float2*)(bias + col);
                float v0 = acc[mt][nt][2*half_m]     + bs.x;
                float v1 = acc[mt][nt][2*half_m + 1] + bs.y;
                if (mode == 1) {
                    v0 = fmaxf(v0, 0.f); v1 = fmaxf(v1, 0.f);
                    *(float2*)(g_H1 + rowoff + col) = make_float2(v0, v1);
                } else if (mode == 2) {
                    *(float2*)(g_Y + rowoff + col) = make_float2(gww*v0, gww*v1);
                } else {
                    *(float2*)(outF + rowoff + col) = make_float2(v0, v1);
                }
            }
        }
    }
}

// ---------------- host -------------------------------------------------------
extern "C" void kernel_launch(void* const* d_in, const int* in_sizes, int n_in,
                              void* d_out, int out_size)
{
    (void)in_sizes; (void)n_in; (void)out_size;
    const float* x      = (const float*)d_in[0];
    const float* w_in   = (const float*)d_in[1];
    const float* b_in   = (const float*)d_in[2];
    const float* gi     = (const float*)d_in[3];
    const float* bi     = (const float*)d_in[4];
    const float* g_lnp  = (const float*)d_in[5];
    const float* be_lnp = (const float*)d_in[6];
    const float* wgp    = (const float*)d_in[7];
    const float* w1p    = (const float*)d_in[8];
    const float* b1p    = (const float*)d_in[9];
    const float* w2p    = (const float*)d_in[10];
    const float* b2p    = (const float*)d_in[11];
    const float* w_out  = (const float*)d_in[12];
    const float* b_out  = (const float*)d_in[13];
    const float* g_o    = (const float*)d_in[14];
    const float* be_o   = (const float*)d_in[15];

    float *hP, *tmpP, *xlnP, *h1P, *YP;
    cudaGetSymbolAddress((void**)&hP,   g_h);
    cudaGetSymbolAddress((void**)&tmpP, g_tmp);
    cudaGetSymbolAddress((void**)&xlnP, g_xln);
    cudaGetSymbolAddress((void**)&h1P,  g_H1);
    cudaGetSymbolAddress((void**)&YP,   g_Y);

    cudaFuncSetAttribute(hm_gemm, cudaFuncAttributeMaxDynamicSharedMemorySize, SMEM_DYN);

    zero_k<<<1, 64>>>();

    // input projection + LN -> residual h
    hm_gemm<<<dim3(DIM/128, NTOK/128), 256, SMEM_DYN>>>(
        0, 0, x, w_in, b_in, tmpP, NTOK, DIM, DIM);
    ln_gate<<<NTOK/8, 256>>>(tmpP, hP, gi, bi, nullptr, 0, nullptr, nullptr);

    for (int l = 0; l < NL; l++) {
        // LN (+ fused combine of previous layer's Y for l>0) + gate
        ln_gate<<<NTOK/8, 256>>>(hP, xlnP, g_lnp + (size_t)l*DIM, be_lnp + (size_t)l*DIM,
                                 wgp + (size_t)l*DIM*NE, l,
                                 (l > 0) ? YP : nullptr, hP);
        scan_scatter<<<1, 1024>>>(l);
        hm_gemm<<<dim3(FF/128, NTOK/128, NE), 256, SMEM_DYN>>>(
            1, l, xlnP, w1p, b1p, nullptr, 0, FF, DIM);
        hm_gemm<<<dim3(DIM/128, NTOK/128, NE), 256, SMEM_DYN>>>(
            2, l, h1P, w2p, b2p, nullptr, 0, DIM, FF);
    }
    combine_k<<<NTOK*DIM/256, 256>>>();   // final layer residual

    // output projection + LN -> d_out
    hm_gemm<<<dim3(DIM/128, NTOK/128), 256, SMEM_DYN>>>(
        0, 0, hP, w_out, b_out, tmpP, NTOK, DIM, DIM);
    ln_gate<<<NTOK/8, 256>>>(tmpP, (float*)d_out, g_o, be_o, nullptr, 0, nullptr, nullptr);
}